// round 9
// baseline (speedup 1.0000x reference)
#include <cuda_runtime.h>

#define NPTS   2097152
#define NSTR   500
#define GRID_R 32
#define NCELLS (GRID_R * GRID_R * GRID_R)   // 32768
#define TPB    256
#define PPT    4
#define PTS_PER_BLOCK (TPB * PPT)   // 1024

typedef unsigned long long ull;
typedef unsigned int uint;

// ---- scratch (__device__ globals: allowed) ----
__device__ float4 g_sortedPts[NPTS];   // pass D: warped coords ; pass E overwrites with {d,r,g,b}
__device__ uint   g_cellRank[NPTS];    // (cell << 17) | rank-within-cell
__device__ uint   g_cursor[NCELLS];    // counts -> exclusive offsets
__device__ float4 g_s0[NSTR];          // {-cx, -cy, cr, cg}
__device__ float4 g_s1[NSTR];          // {cb, dens, -cz, b=5r+0.5}

// ---- f32x2 packed helpers (sm_103a) ----
__device__ __forceinline__ ull pk2(float lo, float hi) {
    ull r; asm("mov.b64 %0, {%1,%2};" : "=l"(r) : "f"(lo), "f"(hi)); return r;
}
__device__ __forceinline__ void upk2(ull v, float& lo, float& hi) {
    asm("mov.b64 {%0,%1}, %2;" : "=f"(lo), "=f"(hi) : "l"(v));
}
__device__ __forceinline__ ull add2(ull a, ull b) {
    ull r; asm("add.rn.f32x2 %0, %1, %2;" : "=l"(r) : "l"(a), "l"(b)); return r;
}
__device__ __forceinline__ ull mul2(ull a, ull b) {
    ull r; asm("mul.rn.f32x2 %0, %1, %2;" : "=l"(r) : "l"(a), "l"(b)); return r;
}
__device__ __forceinline__ ull fma2_(ull a, ull b, ull c) {
    ull r; asm("fma.rn.f32x2 %0, %1, %2, %3;" : "=l"(r) : "l"(a), "l"(b), "l"(c)); return r;
}
__device__ __forceinline__ float sqap(float x) {
    float y; asm("sqrt.approx.f32 %0, %1;" : "=f"(y) : "f"(x)); return y;
}
__device__ __forceinline__ float rcpap(float x) {
    float y; asm("rcp.approx.f32 %0, %1;" : "=f"(y) : "f"(x)); return y;
}
// t = saturate(dist * (-5.0) + b)   -- FFMA-imm form, rt=1
__device__ __forceinline__ float fmasat_m5(float dist, float b) {
    float d; asm("fma.rn.sat.f32 %0, %1, 0fC0A00000, %2;" : "=f"(d) : "f"(dist), "f"(b));
    return d;
}

// spread low 5 bits to positions 0,3,6,9,12
__device__ __forceinline__ uint part1by2(uint x) {
    x &= 0x3FFu;
    x = (x | (x << 16)) & 0x30000FFu;
    x = (x | (x << 8))  & 0x300F00Fu;
    x = (x | (x << 4))  & 0x30C30C3u;
    x = (x | (x << 2))  & 0x9249249u;
    return x;
}

__device__ __forceinline__ void warp_contract(float x, float y, float z,
                                              float& px, float& py, float& pz) {
    float n2 = fmaf(x, x, fmaf(y, y, z * z));
    float n  = sqrtf(n2);
    float scale = 0.5f;
    if (n > 1.0f) scale = (2.0f - 1.0f / n) * (0.5f / n);
    px = x * scale; py = y * scale; pz = z * scale;
}

// ---- Pass A: zero cursors + preprocess strokes ----
__global__ void prep_kernel(const float4* __restrict__ shape,
                            const float*  __restrict__ color,
                            const float*  __restrict__ alpha)
{
    int i = blockIdx.x * blockDim.x + threadIdx.x;
    if (i < NCELLS) g_cursor[i] = 0u;
    if (i < NSTR) {
        float4 sp = shape[i];
        float cr = color[3 * i + 0];
        float cg = color[3 * i + 1];
        float cb = color[3 * i + 2];
        float dens = fmaxf(alpha[i], 0.0f) * 50.0f;
        g_s0[i] = make_float4(-sp.x, -sp.y, cr, cg);
        g_s1[i] = make_float4(cb, dens, -sp.z, fmaf(sp.w, 5.0f, 0.5f));
    }
}

// ---- Pass B: warp coords, write coords output, bin-count + capture rank ----
__global__ __launch_bounds__(TPB)
void bin_kernel(const float* __restrict__ coords, float* __restrict__ out)
{
    int i = blockIdx.x * TPB + threadIdx.x;
    float px, py, pz;
    warp_contract(coords[3 * i + 0], coords[3 * i + 1], coords[3 * i + 2], px, py, pz);

    out[4 * NPTS + 3 * i + 0] = px;
    out[4 * NPTS + 3 * i + 1] = py;
    out[4 * NPTS + 3 * i + 2] = pz;

    uint ix = (uint)min(GRID_R - 1, max(0, (int)((px + 1.0f) * 16.0f)));
    uint iy = (uint)min(GRID_R - 1, max(0, (int)((py + 1.0f) * 16.0f)));
    uint iz = (uint)min(GRID_R - 1, max(0, (int)((pz + 1.0f) * 16.0f)));
    uint cell = part1by2(ix) | (part1by2(iy) << 1) | (part1by2(iz) << 2);
    uint rank = atomicAdd(&g_cursor[cell], 1u);
    g_cellRank[i] = (cell << 17) | rank;
}

// ---- Pass C: single-block exclusive scan of 32768 counts (in place) ----
__global__ __launch_bounds__(1024)
void scan_kernel()
{
    __shared__ uint warpsum[32];
    const int t = threadIdx.x;
    const int lane = t & 31, wid = t >> 5;
    const int PER = NCELLS / 1024;   // 32

    uint v[PER];
    uint base_i = (uint)t * PER;
    uint local = 0;
#pragma unroll
    for (int j = 0; j < PER; j++) { v[j] = g_cursor[base_i + j]; local += v[j]; }

    uint x = local;
#pragma unroll
    for (int d = 1; d < 32; d <<= 1) {
        uint y = __shfl_up_sync(0xffffffffu, x, d);
        if (lane >= d) x += y;
    }
    if (lane == 31) warpsum[wid] = x;
    __syncthreads();
    if (wid == 0) {
        uint w = warpsum[lane];
#pragma unroll
        for (int d = 1; d < 32; d <<= 1) {
            uint y = __shfl_up_sync(0xffffffffu, w, d);
            if (lane >= d) w += y;
        }
        warpsum[lane] = w;
    }
    __syncthreads();
    uint base = (wid ? warpsum[wid - 1] : 0u) + (x - local);
#pragma unroll
    for (int j = 0; j < PER; j++) {
        g_cursor[base_i + j] = base;
        base += v[j];
    }
}

// ---- Pass D: ATOMIC-FREE scatter: pos = offset[cell] + rank; 8 pts/thread ----
__global__ __launch_bounds__(TPB)
void scatter_kernel(const float* __restrict__ coords)
{
    int g = blockIdx.x * TPB + threadIdx.x;
    float4 c4[6];
#pragma unroll
    for (int j = 0; j < 6; j++) c4[j] = ((const float4*)coords)[g * 6 + j];
    const float* cf = (const float*)c4;

    uint4 ra = ((const uint4*)g_cellRank)[g * 2 + 0];
    uint4 rb = ((const uint4*)g_cellRank)[g * 2 + 1];
    uint pk[8] = {ra.x, ra.y, ra.z, ra.w, rb.x, rb.y, rb.z, rb.w};

    uint pos[8];
#pragma unroll
    for (int j = 0; j < 8; j++)
        pos[j] = g_cursor[pk[j] >> 17] + (pk[j] & 0x1FFFFu);
#pragma unroll
    for (int j = 0; j < 8; j++) {
        float px, py, pz;
        warp_contract(cf[3 * j + 0], cf[3 * j + 1], cf[3 * j + 2], px, py, pz);
        g_sortedPts[pos[j]] = make_float4(px, py, pz, 0.0f);
    }
}

// ---- Pass E: main blend; writes results IN SORTED ORDER (coalesced, in place) ----
__global__ __launch_bounds__(TPB)
void main_kernel()
{
    __shared__ float4 cs0[NSTR];
    __shared__ float4 cs1[NSTR];
    __shared__ short  wlist[8][NSTR]; // per-warp surviving stroke indices
    __shared__ uint   wcnt[8];
    __shared__ float  red[8][6];

    const int tid = threadIdx.x;
    const int lane = tid & 31, wid = tid >> 5;
    const int base = blockIdx.x * PTS_PER_BLOCK + tid;

    ull   pxy[PPT];
    float pz [PPT];
    ull   hrg[PPT];
    ull   hbd[PPT];
    float w  [PPT];

    float mnx =  1e30f, mny =  1e30f, mnz =  1e30f;
    float mxx = -1e30f, mxy = -1e30f, mxz = -1e30f;

#pragma unroll
    for (int k = 0; k < PPT; k++) {
        float4 p = g_sortedPts[base + k * TPB];
        pxy[k] = pk2(p.x, p.y);
        pz [k] = p.z;
        hrg[k] = 0ULL; hbd[k] = 0ULL; w[k] = 1.0f;
        mnx = fminf(mnx, p.x); mxx = fmaxf(mxx, p.x);
        mny = fminf(mny, p.y); mxy = fmaxf(mxy, p.y);
        mnz = fminf(mnz, p.z); mxz = fmaxf(mxz, p.z);
    }

    // warp bbox (registers; uniform across the warp after reduce)
#pragma unroll
    for (int d = 16; d; d >>= 1) {
        mnx = fminf(mnx, __shfl_xor_sync(0xffffffffu, mnx, d));
        mny = fminf(mny, __shfl_xor_sync(0xffffffffu, mny, d));
        mnz = fminf(mnz, __shfl_xor_sync(0xffffffffu, mnz, d));
        mxx = fmaxf(mxx, __shfl_xor_sync(0xffffffffu, mxx, d));
        mxy = fmaxf(mxy, __shfl_xor_sync(0xffffffffu, mxy, d));
        mxz = fmaxf(mxz, __shfl_xor_sync(0xffffffffu, mxz, d));
    }
    const float wmnx = mnx, wmny = mny, wmnz = mnz;
    const float wmxx = mxx, wmxy = mxy, wmxz = mxz;

    // block bbox for block-level compaction
    if (lane == 0) {
        red[wid][0] = mnx; red[wid][1] = mny; red[wid][2] = mnz;
        red[wid][3] = mxx; red[wid][4] = mxy; red[wid][5] = mxz;
    }
    __syncthreads();
#pragma unroll
    for (int ww = 0; ww < 8; ww++) {
        mnx = fminf(mnx, red[ww][0]); mny = fminf(mny, red[ww][1]); mnz = fminf(mnz, red[ww][2]);
        mxx = fmaxf(mxx, red[ww][3]); mxy = fmaxf(mxy, red[ww][4]); mxz = fmaxf(mxz, red[ww][5]);
    }
    __syncthreads();

    // ordered block compaction of strokes intersecting the BLOCK bbox
    int nlist = 0;
#pragma unroll 1
    for (int r = 0; r < 2; r++) {
        int s = r * TPB + tid;
        bool keep = false;
        float4 a0, a1;
        if (s < NSTR) {
            a0 = g_s0[s]; a1 = g_s1[s];
            float cx = -a0.x, cy = -a0.y, cz = -a1.z;
            float rr = a1.w * a1.w * 0.04f;   // (b/5)^2 = (r+0.1)^2
            float qx = fminf(fmaxf(cx, mnx), mxx);
            float qy = fminf(fmaxf(cy, mny), mxy);
            float qz = fminf(fmaxf(cz, mnz), mxz);
            float dx = cx - qx, dy = cy - qy, dz = cz - qz;
            float d2 = fmaf(dx, dx, fmaf(dy, dy, dz * dz));
            keep = d2 < rr;
        }
        uint m = __ballot_sync(0xffffffffu, keep);
        if (lane == 0) wcnt[wid] = (uint)__popc(m);
        __syncthreads();
        int off = nlist, tot = nlist;
#pragma unroll
        for (int ww = 0; ww < 8; ww++) {
            if (ww < wid) off += (int)wcnt[ww];
            tot += (int)wcnt[ww];
        }
        if (keep) {
            int pos = off + __popc(m & ((1u << lane) - 1u));
            cs0[pos] = a0;
            cs1[pos] = a1;
        }
        nlist = tot;
        __syncthreads();
    }

    // per-warp index compaction against the WARP bbox
    int wn = 0;
#pragma unroll 1
    for (int s0 = 0; s0 < nlist; s0 += 32) {
        int s = s0 + lane;
        bool keep = false;
        if (s < nlist) {
            float4 a0 = cs0[s];
            float4 a1 = cs1[s];
            float cx = -a0.x, cy = -a0.y, cz = -a1.z;
            float rr = a1.w * a1.w * 0.04f;
            float qx = fminf(fmaxf(cx, wmnx), wmxx);
            float qy = fminf(fmaxf(cy, wmny), wmxy);
            float qz = fminf(fmaxf(cz, wmnz), wmxz);
            float dx = cx - qx, dy = cy - qy, dz = cz - qz;
            float d2 = fmaf(dx, dx, fmaf(dy, dy, dz * dz));
            keep = d2 < rr;
        }
        uint m = __ballot_sync(0xffffffffu, keep);
        if (keep)
            wlist[wid][wn + __popc(m & ((1u << lane) - 1u))] = (short)s;
        wn += __popc(m);
    }

    // sequential blend over this warp's survivors (order preserved), test-free
#pragma unroll 1
    for (int j = 0; j < wn; j++) {
        int s = wlist[wid][j];
        float4 s0 = cs0[s];
        float4 s1 = cs1[s];
        ull ncxy = pk2(s0.x, s0.y);
        ull crg  = pk2(s0.z, s0.w);
        ull cbd  = pk2(s1.x, s1.y);
        float ncz = s1.z;
        float bb  = s1.w;
#pragma unroll
        for (int k = 0; k < PPT; k++) {
            ull dxy = add2(pxy[k], ncxy);
            float dz = pz[k] + ncz;
            ull sq  = mul2(dxy, dxy);
            float lo, hi; upk2(sq, lo, hi);
            float d2 = fmaf(dz, dz, hi) + lo;
            float dist = sqap(d2);
            float t  = fmasat_m5(dist, bb);
            float nt = -t;
            ull t2  = pk2(t, t);
            ull nt2 = pk2(nt, nt);
            hrg[k] = fma2_(t2, crg, fma2_(nt2, hrg[k], hrg[k]));
            hbd[k] = fma2_(t2, cbd, fma2_(nt2, hbd[k], hbd[k]));
            w[k]   = fmaf(nt, w[k], w[k]);
        }
    }

    // write {density, r, g, b} back IN SORTED ORDER (coalesced, in place)
#pragma unroll
    for (int k = 0; k < PPT; k++) {
        float hr, hg, hb, hd;
        upk2(hrg[k], hr, hg);
        upk2(hbd[k], hb, hd);
        float inv = rcpap(1.0f + 1e-6f - w[k]);
        g_sortedPts[base + k * TPB] = make_float4(
            hd,
            __saturatef(hr * inv),
            __saturatef(hg * inv),
            __saturatef(hb * inv));
    }
}

// ---- Pass F: unsort — gather sorted results back to original order (coalesced out) ----
__global__ __launch_bounds__(TPB)
void unsort_kernel(float* __restrict__ out)
{
    int g = blockIdx.x * TPB + threadIdx.x;
    int i0 = g * 8;

    uint4 ra = ((const uint4*)g_cellRank)[g * 2 + 0];
    uint4 rb = ((const uint4*)g_cellRank)[g * 2 + 1];
    uint pk[8] = {ra.x, ra.y, ra.z, ra.w, rb.x, rb.y, rb.z, rb.w};

    uint pos[8];
#pragma unroll
    for (int j = 0; j < 8; j++)
        pos[j] = g_cursor[pk[j] >> 17] + (pk[j] & 0x1FFFFu);

    float4 v[8];
#pragma unroll
    for (int j = 0; j < 8; j++) v[j] = g_sortedPts[pos[j]];   // MLP-8 gather (L2-resident)

#pragma unroll
    for (int j = 0; j < 8; j++) {
        int i = i0 + j;
        out[i] = v[j].x;
        out[NPTS + 3 * i + 0] = v[j].y;
        out[NPTS + 3 * i + 1] = v[j].z;
        out[NPTS + 3 * i + 2] = v[j].w;
    }
}

extern "C" void kernel_launch(void* const* d_in, const int* in_sizes, int n_in,
                              void* d_out, int out_size)
{
    const float*  coords = (const float*)d_in[0];
    const float4* shape  = (const float4*)d_in[1];
    const float*  color  = (const float*)d_in[2];
    const float*  alpha  = (const float*)d_in[3];
    float* out = (float*)d_out;

    prep_kernel<<<(NCELLS + TPB - 1) / TPB, TPB>>>(shape, color, alpha);
    bin_kernel<<<NPTS / TPB, TPB>>>(coords, out);
    scan_kernel<<<1, 1024>>>();
    scatter_kernel<<<NPTS / (TPB * 8), TPB>>>(coords);
    main_kernel<<<NPTS / PTS_PER_BLOCK, TPB>>>();
    unsort_kernel<<<NPTS / (TPB * 8), TPB>>>(out);
}

// round 10
// speedup vs baseline: 1.0195x; 1.0195x over previous
#include <cuda_runtime.h>

#define NPTS   2097152
#define NSTR   500
#define GRID_R 32
#define NCELLS (GRID_R * GRID_R * GRID_R)   // 32768
#define TPB    256
#define PPT    4
#define PTS_PER_BLOCK (TPB * PPT)   // 1024
#define NCHUNKS (NPTS / PTS_PER_BLOCK)      // 2048
#define PERSIST_BLOCKS 1184                 // 148 SMs * 8 blocks

typedef unsigned long long ull;
typedef unsigned int uint;

// ---- scratch (__device__ globals: allowed) ----
__device__ float4 g_sortedPts[NPTS];   // warped coords, w = orig index (bitcast)
__device__ uint   g_cellRank[NPTS];    // (cell << 17) | rank-within-cell
__device__ uint   g_cursor[NCELLS];    // counts -> exclusive offsets
__device__ float4 g_s0[NSTR];          // {-cx, -cy, cr, cg}
__device__ float4 g_s1[NSTR];          // {cb, dens, -cz, b=5r+0.5}
__device__ uint   g_work;              // dynamic chunk queue head

// ---- f32x2 packed helpers (sm_103a) ----
__device__ __forceinline__ ull pk2(float lo, float hi) {
    ull r; asm("mov.b64 %0, {%1,%2};" : "=l"(r) : "f"(lo), "f"(hi)); return r;
}
__device__ __forceinline__ void upk2(ull v, float& lo, float& hi) {
    asm("mov.b64 {%0,%1}, %2;" : "=f"(lo), "=f"(hi) : "l"(v));
}
__device__ __forceinline__ ull add2(ull a, ull b) {
    ull r; asm("add.rn.f32x2 %0, %1, %2;" : "=l"(r) : "l"(a), "l"(b)); return r;
}
__device__ __forceinline__ ull mul2(ull a, ull b) {
    ull r; asm("mul.rn.f32x2 %0, %1, %2;" : "=l"(r) : "l"(a), "l"(b)); return r;
}
__device__ __forceinline__ ull fma2_(ull a, ull b, ull c) {
    ull r; asm("fma.rn.f32x2 %0, %1, %2, %3;" : "=l"(r) : "l"(a), "l"(b), "l"(c)); return r;
}
__device__ __forceinline__ float sqap(float x) {
    float y; asm("sqrt.approx.f32 %0, %1;" : "=f"(y) : "f"(x)); return y;
}
// t = saturate(dist * (-5.0) + b)   -- FFMA-imm form, rt=1
__device__ __forceinline__ float fmasat_m5(float dist, float b) {
    float d; asm("fma.rn.sat.f32 %0, %1, 0fC0A00000, %2;" : "=f"(d) : "f"(dist), "f"(b));
    return d;
}

// spread low 5 bits to positions 0,3,6,9,12
__device__ __forceinline__ uint part1by2(uint x) {
    x &= 0x3FFu;
    x = (x | (x << 16)) & 0x30000FFu;
    x = (x | (x << 8))  & 0x300F00Fu;
    x = (x | (x << 4))  & 0x30C30C3u;
    x = (x | (x << 2))  & 0x9249249u;
    return x;
}

__device__ __forceinline__ void warp_contract(float x, float y, float z,
                                              float& px, float& py, float& pz) {
    float n2 = fmaf(x, x, fmaf(y, y, z * z));
    float n  = sqrtf(n2);
    float scale = 0.5f;
    if (n > 1.0f) scale = (2.0f - 1.0f / n) * (0.5f / n);
    px = x * scale; py = y * scale; pz = z * scale;
}

// ---- Pass A: zero cursors + work queue + preprocess strokes ----
__global__ void prep_kernel(const float4* __restrict__ shape,
                            const float*  __restrict__ color,
                            const float*  __restrict__ alpha)
{
    int i = blockIdx.x * blockDim.x + threadIdx.x;
    if (i == 0) g_work = 0u;
    if (i < NCELLS) g_cursor[i] = 0u;
    if (i < NSTR) {
        float4 sp = shape[i];
        float cr = color[3 * i + 0];
        float cg = color[3 * i + 1];
        float cb = color[3 * i + 2];
        float dens = fmaxf(alpha[i], 0.0f) * 50.0f;
        g_s0[i] = make_float4(-sp.x, -sp.y, cr, cg);
        g_s1[i] = make_float4(cb, dens, -sp.z, fmaf(sp.w, 5.0f, 0.5f));
    }
}

// ---- Pass B: warp coords, write coords output, bin-count + capture rank ----
__global__ __launch_bounds__(TPB)
void bin_kernel(const float* __restrict__ coords, float* __restrict__ out)
{
    int i = blockIdx.x * TPB + threadIdx.x;
    float px, py, pz;
    warp_contract(coords[3 * i + 0], coords[3 * i + 1], coords[3 * i + 2], px, py, pz);

    out[4 * NPTS + 3 * i + 0] = px;
    out[4 * NPTS + 3 * i + 1] = py;
    out[4 * NPTS + 3 * i + 2] = pz;

    uint ix = (uint)min(GRID_R - 1, max(0, (int)((px + 1.0f) * 16.0f)));
    uint iy = (uint)min(GRID_R - 1, max(0, (int)((py + 1.0f) * 16.0f)));
    uint iz = (uint)min(GRID_R - 1, max(0, (int)((pz + 1.0f) * 16.0f)));
    uint cell = part1by2(ix) | (part1by2(iy) << 1) | (part1by2(iz) << 2);
    uint rank = atomicAdd(&g_cursor[cell], 1u);
    g_cellRank[i] = (cell << 17) | rank;
}

// ---- Pass C: single-block exclusive scan of 32768 counts (in place) ----
__global__ __launch_bounds__(1024)
void scan_kernel()
{
    __shared__ uint warpsum[32];
    const int t = threadIdx.x;
    const int lane = t & 31, wid = t >> 5;
    const int PER = NCELLS / 1024;   // 32

    uint v[PER];
    uint base_i = (uint)t * PER;
    uint local = 0;
#pragma unroll
    for (int j = 0; j < PER; j++) { v[j] = g_cursor[base_i + j]; local += v[j]; }

    uint x = local;
#pragma unroll
    for (int d = 1; d < 32; d <<= 1) {
        uint y = __shfl_up_sync(0xffffffffu, x, d);
        if (lane >= d) x += y;
    }
    if (lane == 31) warpsum[wid] = x;
    __syncthreads();
    if (wid == 0) {
        uint w = warpsum[lane];
#pragma unroll
        for (int d = 1; d < 32; d <<= 1) {
            uint y = __shfl_up_sync(0xffffffffu, w, d);
            if (lane >= d) w += y;
        }
        warpsum[lane] = w;
    }
    __syncthreads();
    uint base = (wid ? warpsum[wid - 1] : 0u) + (x - local);
#pragma unroll
    for (int j = 0; j < PER; j++) {
        g_cursor[base_i + j] = base;
        base += v[j];
    }
}

// ---- Pass D: ATOMIC-FREE scatter: pos = offset[cell] + rank; 8 pts/thread ----
__global__ __launch_bounds__(TPB)
void scatter_kernel(const float* __restrict__ coords)
{
    int g = blockIdx.x * TPB + threadIdx.x;
    int i0 = g * 8;
    float4 c4[6];
#pragma unroll
    for (int j = 0; j < 6; j++) c4[j] = ((const float4*)coords)[g * 6 + j];
    const float* cf = (const float*)c4;

    uint4 ra = ((const uint4*)g_cellRank)[g * 2 + 0];
    uint4 rb = ((const uint4*)g_cellRank)[g * 2 + 1];
    uint pk[8] = {ra.x, ra.y, ra.z, ra.w, rb.x, rb.y, rb.z, rb.w};

    uint pos[8];
#pragma unroll
    for (int j = 0; j < 8; j++)
        pos[j] = g_cursor[pk[j] >> 17] + (pk[j] & 0x1FFFFu);
#pragma unroll
    for (int j = 0; j < 8; j++) {
        float px, py, pz;
        warp_contract(cf[3 * j + 0], cf[3 * j + 1], cf[3 * j + 2], px, py, pz);
        g_sortedPts[pos[j]] = make_float4(px, py, pz, __int_as_float(i0 + j));
    }
}

// ---- Pass E: PERSISTENT main blend; dynamic chunk queue ----
__global__ __launch_bounds__(TPB)
void main_kernel(float* __restrict__ out)
{
    __shared__ float4 cs0[NSTR];
    __shared__ float4 cs1[NSTR];
    __shared__ short  wlist[8][NSTR]; // per-warp surviving stroke indices
    __shared__ uint   wcnt[8];
    __shared__ float  red[8][6];
    __shared__ uint   sblk;

    const int tid = threadIdx.x;
    const int lane = tid & 31, wid = tid >> 5;

    for (;;) {
        if (tid == 0) sblk = atomicAdd(&g_work, 1u);
        __syncthreads();
        uint blk = sblk;
        if (blk >= NCHUNKS) break;
        __syncthreads();   // smem reuse guard before compaction overwrites

        const int base = (int)blk * PTS_PER_BLOCK + tid;

        ull   pxy[PPT];
        float pz [PPT];
        int   orig[PPT];
        ull   hrg[PPT];
        ull   hbd[PPT];
        float w  [PPT];

        float mnx =  1e30f, mny =  1e30f, mnz =  1e30f;
        float mxx = -1e30f, mxy = -1e30f, mxz = -1e30f;

#pragma unroll
        for (int k = 0; k < PPT; k++) {
            float4 p = g_sortedPts[base + k * TPB];
            pxy[k] = pk2(p.x, p.y);
            pz [k] = p.z;
            orig[k] = __float_as_int(p.w);
            hrg[k] = 0ULL; hbd[k] = 0ULL; w[k] = 1.0f;
            mnx = fminf(mnx, p.x); mxx = fmaxf(mxx, p.x);
            mny = fminf(mny, p.y); mxy = fmaxf(mxy, p.y);
            mnz = fminf(mnz, p.z); mxz = fmaxf(mxz, p.z);
        }

        // warp bbox
#pragma unroll
        for (int d = 16; d; d >>= 1) {
            mnx = fminf(mnx, __shfl_xor_sync(0xffffffffu, mnx, d));
            mny = fminf(mny, __shfl_xor_sync(0xffffffffu, mny, d));
            mnz = fminf(mnz, __shfl_xor_sync(0xffffffffu, mnz, d));
            mxx = fmaxf(mxx, __shfl_xor_sync(0xffffffffu, mxx, d));
            mxy = fmaxf(mxy, __shfl_xor_sync(0xffffffffu, mxy, d));
            mxz = fmaxf(mxz, __shfl_xor_sync(0xffffffffu, mxz, d));
        }
        const float wmnx = mnx, wmny = mny, wmnz = mnz;
        const float wmxx = mxx, wmxy = mxy, wmxz = mxz;

        // block bbox
        if (lane == 0) {
            red[wid][0] = mnx; red[wid][1] = mny; red[wid][2] = mnz;
            red[wid][3] = mxx; red[wid][4] = mxy; red[wid][5] = mxz;
        }
        __syncthreads();
#pragma unroll
        for (int ww = 0; ww < 8; ww++) {
            mnx = fminf(mnx, red[ww][0]); mny = fminf(mny, red[ww][1]); mnz = fminf(mnz, red[ww][2]);
            mxx = fmaxf(mxx, red[ww][3]); mxy = fmaxf(mxy, red[ww][4]); mxz = fmaxf(mxz, red[ww][5]);
        }
        __syncthreads();

        // ordered block compaction of strokes intersecting the BLOCK bbox
        int nlist = 0;
#pragma unroll 1
        for (int r = 0; r < 2; r++) {
            int s = r * TPB + tid;
            bool keep = false;
            float4 a0, a1;
            if (s < NSTR) {
                a0 = g_s0[s]; a1 = g_s1[s];
                float cx = -a0.x, cy = -a0.y, cz = -a1.z;
                float rr = a1.w * a1.w * 0.04f;   // (r+0.1)^2
                float qx = fminf(fmaxf(cx, mnx), mxx);
                float qy = fminf(fmaxf(cy, mny), mxy);
                float qz = fminf(fmaxf(cz, mnz), mxz);
                float dx = cx - qx, dy = cy - qy, dz = cz - qz;
                float d2 = fmaf(dx, dx, fmaf(dy, dy, dz * dz));
                keep = d2 < rr;
            }
            uint m = __ballot_sync(0xffffffffu, keep);
            if (lane == 0) wcnt[wid] = (uint)__popc(m);
            __syncthreads();
            int off = nlist, tot = nlist;
#pragma unroll
            for (int ww = 0; ww < 8; ww++) {
                if (ww < wid) off += (int)wcnt[ww];
                tot += (int)wcnt[ww];
            }
            if (keep) {
                int pos = off + __popc(m & ((1u << lane) - 1u));
                cs0[pos] = a0;
                cs1[pos] = a1;
            }
            nlist = tot;
            __syncthreads();
        }

        // per-warp index compaction against the WARP bbox
        int wn = 0;
#pragma unroll 1
        for (int s0 = 0; s0 < nlist; s0 += 32) {
            int s = s0 + lane;
            bool keep = false;
            if (s < nlist) {
                float4 a0 = cs0[s];
                float4 a1 = cs1[s];
                float cx = -a0.x, cy = -a0.y, cz = -a1.z;
                float rr = a1.w * a1.w * 0.04f;
                float qx = fminf(fmaxf(cx, wmnx), wmxx);
                float qy = fminf(fmaxf(cy, wmny), wmxy);
                float qz = fminf(fmaxf(cz, wmnz), wmxz);
                float dx = cx - qx, dy = cy - qy, dz = cz - qz;
                float d2 = fmaf(dx, dx, fmaf(dy, dy, dz * dz));
                keep = d2 < rr;
            }
            uint m = __ballot_sync(0xffffffffu, keep);
            if (keep)
                wlist[wid][wn + __popc(m & ((1u << lane) - 1u))] = (short)s;
            wn += __popc(m);
        }

        // sequential blend (order preserved), test-free
#pragma unroll 1
        for (int j = 0; j < wn; j++) {
            int s = wlist[wid][j];
            float4 s0 = cs0[s];
            float4 s1 = cs1[s];
            ull ncxy = pk2(s0.x, s0.y);
            ull crg  = pk2(s0.z, s0.w);
            ull cbd  = pk2(s1.x, s1.y);
            float ncz = s1.z;
            float bb  = s1.w;
#pragma unroll
            for (int k = 0; k < PPT; k++) {
                ull dxy = add2(pxy[k], ncxy);
                float dz = pz[k] + ncz;
                ull sq  = mul2(dxy, dxy);
                float lo, hi; upk2(sq, lo, hi);
                float d2 = fmaf(dz, dz, hi) + lo;
                float dist = sqap(d2);
                float t  = fmasat_m5(dist, bb);
                float nt = -t;
                ull t2  = pk2(t, t);
                ull nt2 = pk2(nt, nt);
                hrg[k] = fma2_(t2, crg, fma2_(nt2, hrg[k], hrg[k]));
                hbd[k] = fma2_(t2, cbd, fma2_(nt2, hbd[k], hbd[k]));
                w[k]   = fmaf(nt, w[k], w[k]);
            }
        }

#pragma unroll
        for (int k = 0; k < PPT; k++) {
            int i = orig[k];
            float hr, hg, hb, hd;
            upk2(hrg[k], hr, hg);
            upk2(hbd[k], hb, hd);
            out[i] = hd;
            float inv = 1.0f / (1.0f + 1e-6f - w[k]);
            out[NPTS + 3 * i + 0] = __saturatef(hr * inv);
            out[NPTS + 3 * i + 1] = __saturatef(hg * inv);
            out[NPTS + 3 * i + 2] = __saturatef(hb * inv);
        }
    }
}

extern "C" void kernel_launch(void* const* d_in, const int* in_sizes, int n_in,
                              void* d_out, int out_size)
{
    const float*  coords = (const float*)d_in[0];
    const float4* shape  = (const float4*)d_in[1];
    const float*  color  = (const float*)d_in[2];
    const float*  alpha  = (const float*)d_in[3];
    float* out = (float*)d_out;

    prep_kernel<<<(NCELLS + TPB - 1) / TPB, TPB>>>(shape, color, alpha);
    bin_kernel<<<NPTS / TPB, TPB>>>(coords, out);
    scan_kernel<<<1, 1024>>>();
    scatter_kernel<<<NPTS / (TPB * 8), TPB>>>(coords);
    main_kernel<<<PERSIST_BLOCKS, TPB>>>(out);
}

// round 11
// speedup vs baseline: 1.1377x; 1.1159x over previous
#include <cuda_runtime.h>

#define NPTS   2097152
#define NSTR   500
#define GRID_R 32
#define NCELLS (GRID_R * GRID_R * GRID_R)   // 32768
#define TPB    256
#define PPT    4
#define PTS_PER_BLOCK (TPB * PPT)   // 1024

typedef unsigned long long ull;
typedef unsigned int uint;

// ---- scratch (__device__ globals: allowed) ----
__device__ float4 g_sortedPts[NPTS];   // warped coords, w = orig index (bitcast)
__device__ uint   g_cellRank[NPTS];    // (cell << 17) | rank-within-cell
__device__ uint   g_cursor[NCELLS];    // counts -> exclusive offsets
__device__ float4 g_s0[NSTR];          // {-cx, -cy, cr, cg}
__device__ float4 g_s1[NSTR];          // {cb, dens, -cz, b=5r+0.5}

// ---- f32x2 packed helpers (sm_103a) ----
__device__ __forceinline__ ull pk2(float lo, float hi) {
    ull r; asm("mov.b64 %0, {%1,%2};" : "=l"(r) : "f"(lo), "f"(hi)); return r;
}
__device__ __forceinline__ void upk2(ull v, float& lo, float& hi) {
    asm("mov.b64 {%0,%1}, %2;" : "=f"(lo), "=f"(hi) : "l"(v));
}
__device__ __forceinline__ ull add2(ull a, ull b) {
    ull r; asm("add.rn.f32x2 %0, %1, %2;" : "=l"(r) : "l"(a), "l"(b)); return r;
}
__device__ __forceinline__ ull mul2(ull a, ull b) {
    ull r; asm("mul.rn.f32x2 %0, %1, %2;" : "=l"(r) : "l"(a), "l"(b)); return r;
}
__device__ __forceinline__ ull fma2_(ull a, ull b, ull c) {
    ull r; asm("fma.rn.f32x2 %0, %1, %2, %3;" : "=l"(r) : "l"(a), "l"(b), "l"(c)); return r;
}
__device__ __forceinline__ float sqap(float x) {
    float y; asm("sqrt.approx.f32 %0, %1;" : "=f"(y) : "f"(x)); return y;
}
// t = saturate(dist * (-5.0) + b)   -- FFMA-imm form, rt=1
__device__ __forceinline__ float fmasat_m5(float dist, float b) {
    float d; asm("fma.rn.sat.f32 %0, %1, 0fC0A00000, %2;" : "=f"(d) : "f"(dist), "f"(b));
    return d;
}

// spread low 5 bits to positions 0,3,6,9,12
__device__ __forceinline__ uint part1by2(uint x) {
    x &= 0x3FFu;
    x = (x | (x << 16)) & 0x30000FFu;
    x = (x | (x << 8))  & 0x300F00Fu;
    x = (x | (x << 4))  & 0x30C30C3u;
    x = (x | (x << 2))  & 0x9249249u;
    return x;
}

__device__ __forceinline__ void warp_contract(float x, float y, float z,
                                              float& px, float& py, float& pz) {
    float n2 = fmaf(x, x, fmaf(y, y, z * z));
    float n  = sqrtf(n2);
    float scale = 0.5f;
    if (n > 1.0f) scale = (2.0f - 1.0f / n) * (0.5f / n);
    px = x * scale; py = y * scale; pz = z * scale;
}

// ---- Pass A: zero cursors + preprocess strokes ----
__global__ void prep_kernel(const float4* __restrict__ shape,
                            const float*  __restrict__ color,
                            const float*  __restrict__ alpha)
{
    int i = blockIdx.x * blockDim.x + threadIdx.x;
    if (i < NCELLS) g_cursor[i] = 0u;
    if (i < NSTR) {
        float4 sp = shape[i];
        float cr = color[3 * i + 0];
        float cg = color[3 * i + 1];
        float cb = color[3 * i + 2];
        float dens = fmaxf(alpha[i], 0.0f) * 50.0f;
        g_s0[i] = make_float4(-sp.x, -sp.y, cr, cg);
        g_s1[i] = make_float4(cb, dens, -sp.z, fmaf(sp.w, 5.0f, 0.5f));
    }
}

// ---- Pass B: warp coords, write coords output, bin-count + capture rank ----
__global__ __launch_bounds__(TPB)
void bin_kernel(const float* __restrict__ coords, float* __restrict__ out)
{
    int i = blockIdx.x * TPB + threadIdx.x;
    float px, py, pz;
    warp_contract(coords[3 * i + 0], coords[3 * i + 1], coords[3 * i + 2], px, py, pz);

    out[4 * NPTS + 3 * i + 0] = px;
    out[4 * NPTS + 3 * i + 1] = py;
    out[4 * NPTS + 3 * i + 2] = pz;

    uint ix = (uint)min(GRID_R - 1, max(0, (int)((px + 1.0f) * 16.0f)));
    uint iy = (uint)min(GRID_R - 1, max(0, (int)((py + 1.0f) * 16.0f)));
    uint iz = (uint)min(GRID_R - 1, max(0, (int)((pz + 1.0f) * 16.0f)));
    uint cell = part1by2(ix) | (part1by2(iy) << 1) | (part1by2(iz) << 2);
    uint rank = atomicAdd(&g_cursor[cell], 1u);
    g_cellRank[i] = (cell << 17) | rank;
}

// ---- Pass C: single-block exclusive scan of 32768 counts (in place) ----
__global__ __launch_bounds__(1024)
void scan_kernel()
{
    __shared__ uint warpsum[32];
    const int t = threadIdx.x;
    const int lane = t & 31, wid = t >> 5;
    const int PER = NCELLS / 1024;   // 32

    uint v[PER];
    uint base_i = (uint)t * PER;
    uint local = 0;
#pragma unroll
    for (int j = 0; j < PER; j++) { v[j] = g_cursor[base_i + j]; local += v[j]; }

    uint x = local;
#pragma unroll
    for (int d = 1; d < 32; d <<= 1) {
        uint y = __shfl_up_sync(0xffffffffu, x, d);
        if (lane >= d) x += y;
    }
    if (lane == 31) warpsum[wid] = x;
    __syncthreads();
    if (wid == 0) {
        uint w = warpsum[lane];
#pragma unroll
        for (int d = 1; d < 32; d <<= 1) {
            uint y = __shfl_up_sync(0xffffffffu, w, d);
            if (lane >= d) w += y;
        }
        warpsum[lane] = w;
    }
    __syncthreads();
    uint base = (wid ? warpsum[wid - 1] : 0u) + (x - local);
#pragma unroll
    for (int j = 0; j < PER; j++) {
        g_cursor[base_i + j] = base;
        base += v[j];
    }
}

// ---- Pass D: ATOMIC-FREE scatter: pos = offset[cell] + rank; 8 pts/thread ----
__global__ __launch_bounds__(TPB)
void scatter_kernel(const float* __restrict__ coords)
{
    int g = blockIdx.x * TPB + threadIdx.x;
    int i0 = g * 8;
    float4 c4[6];
#pragma unroll
    for (int j = 0; j < 6; j++) c4[j] = ((const float4*)coords)[g * 6 + j];
    const float* cf = (const float*)c4;

    uint4 ra = ((const uint4*)g_cellRank)[g * 2 + 0];
    uint4 rb = ((const uint4*)g_cellRank)[g * 2 + 1];
    uint pk[8] = {ra.x, ra.y, ra.z, ra.w, rb.x, rb.y, rb.z, rb.w};

    uint pos[8];
#pragma unroll
    for (int j = 0; j < 8; j++)
        pos[j] = g_cursor[pk[j] >> 17] + (pk[j] & 0x1FFFFu);
#pragma unroll
    for (int j = 0; j < 8; j++) {
        float px, py, pz;
        warp_contract(cf[3 * j + 0], cf[3 * j + 1], cf[3 * j + 2], px, py, pz);
        g_sortedPts[pos[j]] = make_float4(px, py, pz, __int_as_float(i0 + j));
    }
}

// ---- Pass E: main blend; block compaction + per-warp lists + FULL-COVER truncation ----
__global__ __launch_bounds__(TPB)
void main_kernel(float* __restrict__ out)
{
    __shared__ float4 cs0[NSTR];
    __shared__ float4 cs1[NSTR];
    __shared__ short  wlist[8][NSTR]; // per-warp surviving stroke indices
    __shared__ uint   wcnt[8];
    __shared__ float  red[8][6];

    const int tid = threadIdx.x;
    const int lane = tid & 31, wid = tid >> 5;
    const int base = blockIdx.x * PTS_PER_BLOCK + tid;

    ull   pxy[PPT];
    float pz [PPT];
    int   orig[PPT];
    ull   hrg[PPT];
    ull   hbd[PPT];
    float w  [PPT];

    float mnx =  1e30f, mny =  1e30f, mnz =  1e30f;
    float mxx = -1e30f, mxy = -1e30f, mxz = -1e30f;

#pragma unroll
    for (int k = 0; k < PPT; k++) {
        float4 p = g_sortedPts[base + k * TPB];
        pxy[k] = pk2(p.x, p.y);
        pz [k] = p.z;
        orig[k] = __float_as_int(p.w);
        hrg[k] = 0ULL; hbd[k] = 0ULL; w[k] = 1.0f;
        mnx = fminf(mnx, p.x); mxx = fmaxf(mxx, p.x);
        mny = fminf(mny, p.y); mxy = fmaxf(mxy, p.y);
        mnz = fminf(mnz, p.z); mxz = fmaxf(mxz, p.z);
    }

    // warp bbox (registers; uniform across the warp after reduce)
#pragma unroll
    for (int d = 16; d; d >>= 1) {
        mnx = fminf(mnx, __shfl_xor_sync(0xffffffffu, mnx, d));
        mny = fminf(mny, __shfl_xor_sync(0xffffffffu, mny, d));
        mnz = fminf(mnz, __shfl_xor_sync(0xffffffffu, mnz, d));
        mxx = fmaxf(mxx, __shfl_xor_sync(0xffffffffu, mxx, d));
        mxy = fmaxf(mxy, __shfl_xor_sync(0xffffffffu, mxy, d));
        mxz = fmaxf(mxz, __shfl_xor_sync(0xffffffffu, mxz, d));
    }
    const float wmnx = mnx, wmny = mny, wmnz = mnz;
    const float wmxx = mxx, wmxy = mxy, wmxz = mxz;

    // block bbox for block-level compaction
    if (lane == 0) {
        red[wid][0] = mnx; red[wid][1] = mny; red[wid][2] = mnz;
        red[wid][3] = mxx; red[wid][4] = mxy; red[wid][5] = mxz;
    }
    __syncthreads();
#pragma unroll
    for (int ww = 0; ww < 8; ww++) {
        mnx = fminf(mnx, red[ww][0]); mny = fminf(mny, red[ww][1]); mnz = fminf(mnz, red[ww][2]);
        mxx = fmaxf(mxx, red[ww][3]); mxy = fmaxf(mxy, red[ww][4]); mxz = fmaxf(mxz, red[ww][5]);
    }
    __syncthreads();

    // ordered block compaction of strokes intersecting the BLOCK bbox
    int nlist = 0;
#pragma unroll 1
    for (int r = 0; r < 2; r++) {
        int s = r * TPB + tid;
        bool keep = false;
        float4 a0, a1;
        if (s < NSTR) {
            a0 = g_s0[s]; a1 = g_s1[s];
            float cx = -a0.x, cy = -a0.y, cz = -a1.z;
            float rr = a1.w * a1.w * 0.04f;   // (b/5)^2 = (r+0.1)^2
            float qx = fminf(fmaxf(cx, mnx), mxx);
            float qy = fminf(fmaxf(cy, mny), mxy);
            float qz = fminf(fmaxf(cz, mnz), mxz);
            float dx = cx - qx, dy = cy - qy, dz = cz - qz;
            float d2 = fmaf(dx, dx, fmaf(dy, dy, dz * dz));
            keep = d2 < rr;
        }
        uint m = __ballot_sync(0xffffffffu, keep);
        if (lane == 0) wcnt[wid] = (uint)__popc(m);
        __syncthreads();
        int off = nlist, tot = nlist;
#pragma unroll
        for (int ww = 0; ww < 8; ww++) {
            if (ww < wid) off += (int)wcnt[ww];
            tot += (int)wcnt[ww];
        }
        if (keep) {
            int pos = off + __popc(m & ((1u << lane) - 1u));
            cs0[pos] = a0;
            cs1[pos] = a1;
        }
        nlist = tot;
        __syncthreads();
    }

    // per-warp index compaction against the WARP bbox + full-cover truncation:
    // if a stroke's (r-0.1)-sphere contains the whole warp bbox, t=1 for every
    // point in the warp -> state fully overwritten -> earlier strokes are dead.
    int wn = 0;
    int wstart = 0;
#pragma unroll 1
    for (int s0 = 0; s0 < nlist; s0 += 32) {
        int s = s0 + lane;
        bool keep = false, cover = false;
        if (s < nlist) {
            float4 a0 = cs0[s];
            float4 a1 = cs1[s];
            float cx = -a0.x, cy = -a0.y, cz = -a1.z;
            float rr = a1.w * a1.w * 0.04f;     // (r+0.1)^2
            float qx = fminf(fmaxf(cx, wmnx), wmxx);
            float qy = fminf(fmaxf(cy, wmny), wmxy);
            float qz = fminf(fmaxf(cz, wmnz), wmxz);
            float dx = cx - qx, dy = cy - qy, dz = cz - qz;
            float d2 = fmaf(dx, dx, fmaf(dy, dy, dz * dz));
            keep = d2 < rr;
            // farthest bbox corner inside radius (r-0.1)?  (b-1) = 5(r-0.1)
            float rm = a1.w - 1.0f;
            float fx = fmaxf(cx - wmnx, wmxx - cx);
            float fy = fmaxf(cy - wmny, wmxy - cy);
            float fz = fmaxf(cz - wmnz, wmxz - cz);
            float f2 = fmaf(fx, fx, fmaf(fy, fy, fz * fz));
            cover = (rm > 0.0f) && (25.0f * f2 < rm * rm);
        }
        uint m  = __ballot_sync(0xffffffffu, keep);
        uint cm = __ballot_sync(0xffffffffu, cover);
        if (keep)
            wlist[wid][wn + __popc(m & ((1u << lane) - 1u))] = (short)s;
        if (cm) {
            int lastLane = 31 - __clz(cm);
            wstart = wn + __popc(m & ((1u << lastLane) - 1u));
        }
        wn += __popc(m);
    }

    // sequential blend from the last full-cover stroke (order preserved)
#pragma unroll 1
    for (int j = wstart; j < wn; j++) {
        int s = wlist[wid][j];
        float4 s0 = cs0[s];
        float4 s1 = cs1[s];
        ull ncxy = pk2(s0.x, s0.y);
        ull crg  = pk2(s0.z, s0.w);
        ull cbd  = pk2(s1.x, s1.y);
        float ncz = s1.z;
        float bb  = s1.w;
#pragma unroll
        for (int k = 0; k < PPT; k++) {
            ull dxy = add2(pxy[k], ncxy);
            float dz = pz[k] + ncz;
            ull sq  = mul2(dxy, dxy);
            float lo, hi; upk2(sq, lo, hi);
            float d2 = fmaf(dz, dz, hi) + lo;
            float dist = sqap(d2);
            float t  = fmasat_m5(dist, bb);
            float nt = -t;
            ull t2  = pk2(t, t);
            ull nt2 = pk2(nt, nt);
            hrg[k] = fma2_(t2, crg, fma2_(nt2, hrg[k], hrg[k]));
            hbd[k] = fma2_(t2, cbd, fma2_(nt2, hbd[k], hbd[k]));
            w[k]   = fmaf(nt, w[k], w[k]);
        }
    }

#pragma unroll
    for (int k = 0; k < PPT; k++) {
        int i = orig[k];
        float hr, hg, hb, hd;
        upk2(hrg[k], hr, hg);
        upk2(hbd[k], hb, hd);
        out[i] = hd;
        float inv = 1.0f / (1.0f + 1e-6f - w[k]);
        out[NPTS + 3 * i + 0] = __saturatef(hr * inv);
        out[NPTS + 3 * i + 1] = __saturatef(hg * inv);
        out[NPTS + 3 * i + 2] = __saturatef(hb * inv);
    }
}

extern "C" void kernel_launch(void* const* d_in, const int* in_sizes, int n_in,
                              void* d_out, int out_size)
{
    const float*  coords = (const float*)d_in[0];
    const float4* shape  = (const float4*)d_in[1];
    const float*  color  = (const float*)d_in[2];
    const float*  alpha  = (const float*)d_in[3];
    float* out = (float*)d_out;

    prep_kernel<<<(NCELLS + TPB - 1) / TPB, TPB>>>(shape, color, alpha);
    bin_kernel<<<NPTS / TPB, TPB>>>(coords, out);
    scan_kernel<<<1, 1024>>>();
    scatter_kernel<<<NPTS / (TPB * 8), TPB>>>(coords);
    main_kernel<<<NPTS / PTS_PER_BLOCK, TPB>>>(out);
}

// round 12
// speedup vs baseline: 1.1971x; 1.0522x over previous
#include <cuda_runtime.h>

#define NPTS   2097152
#define NSTR   500
#define GRID_R 32
#define NCELLS (GRID_R * GRID_R * GRID_R)   // 32768
#define TPB    256
#define PPT    4
#define PTS_PER_BLOCK (TPB * PPT)   // 1024

typedef unsigned long long ull;
typedef unsigned int uint;

// ---- scratch (__device__ globals: allowed) ----
__device__ float4 g_sortedPts[NPTS];   // warped coords, w = orig index (bitcast)
__device__ uint   g_cellRank[NPTS];    // (cell << 17) | rank-within-cell
__device__ uint   g_cursor[NCELLS];    // counts -> exclusive offsets
__device__ float4 g_s0[NSTR];          // {-cx, -cy, cr, cg}
__device__ float4 g_s1[NSTR];          // {cb, dens, -cz, b=5r+0.5}

// ---- f32x2 packed helpers (sm_103a) ----
__device__ __forceinline__ ull pk2(float lo, float hi) {
    ull r; asm("mov.b64 %0, {%1,%2};" : "=l"(r) : "f"(lo), "f"(hi)); return r;
}
__device__ __forceinline__ void upk2(ull v, float& lo, float& hi) {
    asm("mov.b64 {%0,%1}, %2;" : "=f"(lo), "=f"(hi) : "l"(v));
}
__device__ __forceinline__ ull add2(ull a, ull b) {
    ull r; asm("add.rn.f32x2 %0, %1, %2;" : "=l"(r) : "l"(a), "l"(b)); return r;
}
__device__ __forceinline__ ull mul2(ull a, ull b) {
    ull r; asm("mul.rn.f32x2 %0, %1, %2;" : "=l"(r) : "l"(a), "l"(b)); return r;
}
__device__ __forceinline__ ull fma2_(ull a, ull b, ull c) {
    ull r; asm("fma.rn.f32x2 %0, %1, %2, %3;" : "=l"(r) : "l"(a), "l"(b), "l"(c)); return r;
}
__device__ __forceinline__ float sqap(float x) {
    float y; asm("sqrt.approx.f32 %0, %1;" : "=f"(y) : "f"(x)); return y;
}
// t = saturate(dist * (-5.0) + b)   -- FFMA-imm form, rt=1
__device__ __forceinline__ float fmasat_m5(float dist, float b) {
    float d; asm("fma.rn.sat.f32 %0, %1, 0fC0A00000, %2;" : "=f"(d) : "f"(dist), "f"(b));
    return d;
}

// spread low 5 bits to positions 0,3,6,9,12
__device__ __forceinline__ uint part1by2(uint x) {
    x &= 0x3FFu;
    x = (x | (x << 16)) & 0x30000FFu;
    x = (x | (x << 8))  & 0x300F00Fu;
    x = (x | (x << 4))  & 0x30C30C3u;
    x = (x | (x << 2))  & 0x9249249u;
    return x;
}

__device__ __forceinline__ void warp_contract(float x, float y, float z,
                                              float& px, float& py, float& pz) {
    float n2 = fmaf(x, x, fmaf(y, y, z * z));
    float n  = sqrtf(n2);
    float scale = 0.5f;
    if (n > 1.0f) scale = (2.0f - 1.0f / n) * (0.5f / n);
    px = x * scale; py = y * scale; pz = z * scale;
}

// ---- Pass A: zero cursors + preprocess strokes ----
__global__ void prep_kernel(const float4* __restrict__ shape,
                            const float*  __restrict__ color,
                            const float*  __restrict__ alpha)
{
    int i = blockIdx.x * blockDim.x + threadIdx.x;
    if (i < NCELLS) g_cursor[i] = 0u;
    if (i < NSTR) {
        float4 sp = shape[i];
        float cr = color[3 * i + 0];
        float cg = color[3 * i + 1];
        float cb = color[3 * i + 2];
        float dens = fmaxf(alpha[i], 0.0f) * 50.0f;
        g_s0[i] = make_float4(-sp.x, -sp.y, cr, cg);
        g_s1[i] = make_float4(cb, dens, -sp.z, fmaf(sp.w, 5.0f, 0.5f));
    }
}

// ---- Pass B: warp coords, write coords output, bin-count + capture rank ----
__global__ __launch_bounds__(TPB)
void bin_kernel(const float* __restrict__ coords, float* __restrict__ out)
{
    int i = blockIdx.x * TPB + threadIdx.x;
    float px, py, pz;
    warp_contract(coords[3 * i + 0], coords[3 * i + 1], coords[3 * i + 2], px, py, pz);

    out[4 * NPTS + 3 * i + 0] = px;
    out[4 * NPTS + 3 * i + 1] = py;
    out[4 * NPTS + 3 * i + 2] = pz;

    uint ix = (uint)min(GRID_R - 1, max(0, (int)((px + 1.0f) * 16.0f)));
    uint iy = (uint)min(GRID_R - 1, max(0, (int)((py + 1.0f) * 16.0f)));
    uint iz = (uint)min(GRID_R - 1, max(0, (int)((pz + 1.0f) * 16.0f)));
    uint cell = part1by2(ix) | (part1by2(iy) << 1) | (part1by2(iz) << 2);
    uint rank = atomicAdd(&g_cursor[cell], 1u);
    g_cellRank[i] = (cell << 17) | rank;
}

// ---- Pass C: single-block exclusive scan of 32768 counts (in place) ----
__global__ __launch_bounds__(1024)
void scan_kernel()
{
    __shared__ uint warpsum[32];
    const int t = threadIdx.x;
    const int lane = t & 31, wid = t >> 5;
    const int PER = NCELLS / 1024;   // 32

    uint v[PER];
    uint base_i = (uint)t * PER;
    uint local = 0;
#pragma unroll
    for (int j = 0; j < PER; j++) { v[j] = g_cursor[base_i + j]; local += v[j]; }

    uint x = local;
#pragma unroll
    for (int d = 1; d < 32; d <<= 1) {
        uint y = __shfl_up_sync(0xffffffffu, x, d);
        if (lane >= d) x += y;
    }
    if (lane == 31) warpsum[wid] = x;
    __syncthreads();
    if (wid == 0) {
        uint w = warpsum[lane];
#pragma unroll
        for (int d = 1; d < 32; d <<= 1) {
            uint y = __shfl_up_sync(0xffffffffu, w, d);
            if (lane >= d) w += y;
        }
        warpsum[lane] = w;
    }
    __syncthreads();
    uint base = (wid ? warpsum[wid - 1] : 0u) + (x - local);
#pragma unroll
    for (int j = 0; j < PER; j++) {
        g_cursor[base_i + j] = base;
        base += v[j];
    }
}

// ---- Pass D: ATOMIC-FREE scatter: pos = offset[cell] + rank; 8 pts/thread ----
__global__ __launch_bounds__(TPB)
void scatter_kernel(const float* __restrict__ coords)
{
    int g = blockIdx.x * TPB + threadIdx.x;
    int i0 = g * 8;
    float4 c4[6];
#pragma unroll
    for (int j = 0; j < 6; j++) c4[j] = ((const float4*)coords)[g * 6 + j];
    const float* cf = (const float*)c4;

    uint4 ra = ((const uint4*)g_cellRank)[g * 2 + 0];
    uint4 rb = ((const uint4*)g_cellRank)[g * 2 + 1];
    uint pk[8] = {ra.x, ra.y, ra.z, ra.w, rb.x, rb.y, rb.z, rb.w};

    uint pos[8];
#pragma unroll
    for (int j = 0; j < 8; j++)
        pos[j] = g_cursor[pk[j] >> 17] + (pk[j] & 0x1FFFFu);
#pragma unroll
    for (int j = 0; j < 8; j++) {
        float px, py, pz;
        warp_contract(cf[3 * j + 0], cf[3 * j + 1], cf[3 * j + 2], px, py, pz);
        g_sortedPts[pos[j]] = make_float4(px, py, pz, __int_as_float(i0 + j));
    }
}

// ---- Pass E: main blend; warps own CONTIGUOUS 128-point runs ----
__global__ __launch_bounds__(TPB)
void main_kernel(float* __restrict__ out)
{
    __shared__ float4 cs0[NSTR];
    __shared__ float4 cs1[NSTR];
    __shared__ short  wlist[8][NSTR]; // per-warp surviving stroke indices
    __shared__ uint   wcnt[8];
    __shared__ float  red[8][6];

    const int tid = threadIdx.x;
    const int lane = tid & 31, wid = tid >> 5;
    // warp-contiguous layout: warp `wid` owns points [blk*1024 + wid*128, +128)
    const int base = blockIdx.x * PTS_PER_BLOCK + wid * 128 + lane;

    ull   pxy[PPT];
    float pz [PPT];
    int   orig[PPT];
    ull   hrg[PPT];
    ull   hbd[PPT];
    float w  [PPT];

    float mnx =  1e30f, mny =  1e30f, mnz =  1e30f;
    float mxx = -1e30f, mxy = -1e30f, mxz = -1e30f;

#pragma unroll
    for (int k = 0; k < PPT; k++) {
        float4 p = g_sortedPts[base + k * 32];
        pxy[k] = pk2(p.x, p.y);
        pz [k] = p.z;
        orig[k] = __float_as_int(p.w);
        hrg[k] = 0ULL; hbd[k] = 0ULL; w[k] = 1.0f;
        mnx = fminf(mnx, p.x); mxx = fmaxf(mxx, p.x);
        mny = fminf(mny, p.y); mxy = fmaxf(mxy, p.y);
        mnz = fminf(mnz, p.z); mxz = fmaxf(mxz, p.z);
    }

    // warp bbox (now spans only 128 contiguous sorted points -> tight)
#pragma unroll
    for (int d = 16; d; d >>= 1) {
        mnx = fminf(mnx, __shfl_xor_sync(0xffffffffu, mnx, d));
        mny = fminf(mny, __shfl_xor_sync(0xffffffffu, mny, d));
        mnz = fminf(mnz, __shfl_xor_sync(0xffffffffu, mnz, d));
        mxx = fmaxf(mxx, __shfl_xor_sync(0xffffffffu, mxx, d));
        mxy = fmaxf(mxy, __shfl_xor_sync(0xffffffffu, mxy, d));
        mxz = fmaxf(mxz, __shfl_xor_sync(0xffffffffu, mxz, d));
    }
    const float wmnx = mnx, wmny = mny, wmnz = mnz;
    const float wmxx = mxx, wmxy = mxy, wmxz = mxz;

    // block bbox for block-level compaction
    if (lane == 0) {
        red[wid][0] = mnx; red[wid][1] = mny; red[wid][2] = mnz;
        red[wid][3] = mxx; red[wid][4] = mxy; red[wid][5] = mxz;
    }
    __syncthreads();
#pragma unroll
    for (int ww = 0; ww < 8; ww++) {
        mnx = fminf(mnx, red[ww][0]); mny = fminf(mny, red[ww][1]); mnz = fminf(mnz, red[ww][2]);
        mxx = fmaxf(mxx, red[ww][3]); mxy = fmaxf(mxy, red[ww][4]); mxz = fmaxf(mxz, red[ww][5]);
    }
    __syncthreads();

    // ordered block compaction of strokes intersecting the BLOCK bbox
    int nlist = 0;
#pragma unroll 1
    for (int r = 0; r < 2; r++) {
        int s = r * TPB + tid;
        bool keep = false;
        float4 a0, a1;
        if (s < NSTR) {
            a0 = g_s0[s]; a1 = g_s1[s];
            float cx = -a0.x, cy = -a0.y, cz = -a1.z;
            float rr = a1.w * a1.w * 0.04f;   // (b/5)^2 = (r+0.1)^2
            float qx = fminf(fmaxf(cx, mnx), mxx);
            float qy = fminf(fmaxf(cy, mny), mxy);
            float qz = fminf(fmaxf(cz, mnz), mxz);
            float dx = cx - qx, dy = cy - qy, dz = cz - qz;
            float d2 = fmaf(dx, dx, fmaf(dy, dy, dz * dz));
            keep = d2 < rr;
        }
        uint m = __ballot_sync(0xffffffffu, keep);
        if (lane == 0) wcnt[wid] = (uint)__popc(m);
        __syncthreads();
        int off = nlist, tot = nlist;
#pragma unroll
        for (int ww = 0; ww < 8; ww++) {
            if (ww < wid) off += (int)wcnt[ww];
            tot += (int)wcnt[ww];
        }
        if (keep) {
            int pos = off + __popc(m & ((1u << lane) - 1u));
            cs0[pos] = a0;
            cs1[pos] = a1;
        }
        nlist = tot;
        __syncthreads();
    }

    // per-warp index compaction against the (tight) WARP bbox + full-cover truncation
    int wn = 0;
    int wstart = 0;
#pragma unroll 1
    for (int s0 = 0; s0 < nlist; s0 += 32) {
        int s = s0 + lane;
        bool keep = false, cover = false;
        if (s < nlist) {
            float4 a0 = cs0[s];
            float4 a1 = cs1[s];
            float cx = -a0.x, cy = -a0.y, cz = -a1.z;
            float rr = a1.w * a1.w * 0.04f;     // (r+0.1)^2
            float qx = fminf(fmaxf(cx, wmnx), wmxx);
            float qy = fminf(fmaxf(cy, wmny), wmxy);
            float qz = fminf(fmaxf(cz, wmnz), wmxz);
            float dx = cx - qx, dy = cy - qy, dz = cz - qz;
            float d2 = fmaf(dx, dx, fmaf(dy, dy, dz * dz));
            keep = d2 < rr;
            // farthest bbox corner inside radius (r-0.1)?  (b-1) = 5(r-0.1)
            float rm = a1.w - 1.0f;
            float fx = fmaxf(cx - wmnx, wmxx - cx);
            float fy = fmaxf(cy - wmny, wmxy - cy);
            float fz = fmaxf(cz - wmnz, wmxz - cz);
            float f2 = fmaf(fx, fx, fmaf(fy, fy, fz * fz));
            cover = (rm > 0.0f) && (25.0f * f2 < rm * rm);
        }
        uint m  = __ballot_sync(0xffffffffu, keep);
        uint cm = __ballot_sync(0xffffffffu, cover);
        if (keep)
            wlist[wid][wn + __popc(m & ((1u << lane) - 1u))] = (short)s;
        if (cm) {
            int lastLane = 31 - __clz(cm);
            wstart = wn + __popc(m & ((1u << lastLane) - 1u));
        }
        wn += __popc(m);
    }

    // sequential blend from the last full-cover stroke (order preserved)
#pragma unroll 1
    for (int j = wstart; j < wn; j++) {
        int s = wlist[wid][j];
        float4 s0 = cs0[s];
        float4 s1 = cs1[s];
        ull ncxy = pk2(s0.x, s0.y);
        ull crg  = pk2(s0.z, s0.w);
        ull cbd  = pk2(s1.x, s1.y);
        float ncz = s1.z;
        float bb  = s1.w;
#pragma unroll
        for (int k = 0; k < PPT; k++) {
            ull dxy = add2(pxy[k], ncxy);
            float dz = pz[k] + ncz;
            ull sq  = mul2(dxy, dxy);
            float lo, hi; upk2(sq, lo, hi);
            float d2 = fmaf(dz, dz, hi) + lo;
            float dist = sqap(d2);
            float t  = fmasat_m5(dist, bb);
            float nt = -t;
            ull t2  = pk2(t, t);
            ull nt2 = pk2(nt, nt);
            hrg[k] = fma2_(t2, crg, fma2_(nt2, hrg[k], hrg[k]));
            hbd[k] = fma2_(t2, cbd, fma2_(nt2, hbd[k], hbd[k]));
            w[k]   = fmaf(nt, w[k], w[k]);
        }
    }

#pragma unroll
    for (int k = 0; k < PPT; k++) {
        int i = orig[k];
        float hr, hg, hb, hd;
        upk2(hrg[k], hr, hg);
        upk2(hbd[k], hb, hd);
        out[i] = hd;
        float inv = 1.0f / (1.0f + 1e-6f - w[k]);
        out[NPTS + 3 * i + 0] = __saturatef(hr * inv);
        out[NPTS + 3 * i + 1] = __saturatef(hg * inv);
        out[NPTS + 3 * i + 2] = __saturatef(hb * inv);
    }
}

extern "C" void kernel_launch(void* const* d_in, const int* in_sizes, int n_in,
                              void* d_out, int out_size)
{
    const float*  coords = (const float*)d_in[0];
    const float4* shape  = (const float4*)d_in[1];
    const float*  color  = (const float*)d_in[2];
    const float*  alpha  = (const float*)d_in[3];
    float* out = (float*)d_out;

    prep_kernel<<<(NCELLS + TPB - 1) / TPB, TPB>>>(shape, color, alpha);
    bin_kernel<<<NPTS / TPB, TPB>>>(coords, out);
    scan_kernel<<<1, 1024>>>();
    scatter_kernel<<<NPTS / (TPB * 8), TPB>>>(coords);
    main_kernel<<<NPTS / PTS_PER_BLOCK, TPB>>>(out);
}

// round 13
// speedup vs baseline: 1.2356x; 1.0322x over previous
#include <cuda_runtime.h>

#define NPTS   2097152
#define NSTR   500
#define GRID_R 32
#define NCELLS (GRID_R * GRID_R * GRID_R)   // 32768
#define TPB    256
#define PPT    4
#define PTS_PER_BLOCK (TPB * PPT)   // 1024

typedef unsigned long long ull;
typedef unsigned int uint;

// ---- scratch (__device__ globals: allowed) ----
__device__ float4 g_sortedPts[NPTS];   // warped coords, w = orig index (bitcast)
__device__ uint   g_cellRank[NPTS];    // (cell << 17) | rank-within-cell
__device__ uint   g_cursor[NCELLS];    // counts -> exclusive offsets
__device__ float4 g_s0[NSTR];          // {-cx, -cy, cr, cg}
__device__ float4 g_s1[NSTR];          // {cb, dens, -cz, b=5r+0.5}

// ---- f32x2 packed helpers (sm_103a) ----
__device__ __forceinline__ ull pk2(float lo, float hi) {
    ull r; asm("mov.b64 %0, {%1,%2};" : "=l"(r) : "f"(lo), "f"(hi)); return r;
}
__device__ __forceinline__ void upk2(ull v, float& lo, float& hi) {
    asm("mov.b64 {%0,%1}, %2;" : "=f"(lo), "=f"(hi) : "l"(v));
}
__device__ __forceinline__ ull add2(ull a, ull b) {
    ull r; asm("add.rn.f32x2 %0, %1, %2;" : "=l"(r) : "l"(a), "l"(b)); return r;
}
__device__ __forceinline__ ull mul2(ull a, ull b) {
    ull r; asm("mul.rn.f32x2 %0, %1, %2;" : "=l"(r) : "l"(a), "l"(b)); return r;
}
__device__ __forceinline__ ull fma2_(ull a, ull b, ull c) {
    ull r; asm("fma.rn.f32x2 %0, %1, %2, %3;" : "=l"(r) : "l"(a), "l"(b), "l"(c)); return r;
}
__device__ __forceinline__ float sqap(float x) {
    float y; asm("sqrt.approx.f32 %0, %1;" : "=f"(y) : "f"(x)); return y;
}
// t = saturate(dist * (-5.0) + b)   -- FFMA-imm form, rt=1
__device__ __forceinline__ float fmasat_m5(float dist, float b) {
    float d; asm("fma.rn.sat.f32 %0, %1, 0fC0A00000, %2;" : "=f"(d) : "f"(dist), "f"(b));
    return d;
}

// spread low 5 bits to positions 0,3,6,9,12
__device__ __forceinline__ uint part1by2(uint x) {
    x &= 0x3FFu;
    x = (x | (x << 16)) & 0x30000FFu;
    x = (x | (x << 8))  & 0x300F00Fu;
    x = (x | (x << 4))  & 0x30C30C3u;
    x = (x | (x << 2))  & 0x9249249u;
    return x;
}

__device__ __forceinline__ void warp_contract(float x, float y, float z,
                                              float& px, float& py, float& pz) {
    float n2 = fmaf(x, x, fmaf(y, y, z * z));
    float n  = sqrtf(n2);
    float scale = 0.5f;
    if (n > 1.0f) scale = (2.0f - 1.0f / n) * (0.5f / n);
    px = x * scale; py = y * scale; pz = z * scale;
}

// ---- Pass A: zero cursors + preprocess strokes ----
__global__ void prep_kernel(const float4* __restrict__ shape,
                            const float*  __restrict__ color,
                            const float*  __restrict__ alpha)
{
    int i = blockIdx.x * blockDim.x + threadIdx.x;
    if (i < NCELLS) g_cursor[i] = 0u;
    if (i < NSTR) {
        float4 sp = shape[i];
        float cr = color[3 * i + 0];
        float cg = color[3 * i + 1];
        float cb = color[3 * i + 2];
        float dens = fmaxf(alpha[i], 0.0f) * 50.0f;
        g_s0[i] = make_float4(-sp.x, -sp.y, cr, cg);
        g_s1[i] = make_float4(cb, dens, -sp.z, fmaf(sp.w, 5.0f, 0.5f));
    }
}

// ---- Pass B: warp coords, write coords output, bin-count + capture rank ----
__global__ __launch_bounds__(TPB)
void bin_kernel(const float* __restrict__ coords, float* __restrict__ out)
{
    int i = blockIdx.x * TPB + threadIdx.x;
    float px, py, pz;
    warp_contract(coords[3 * i + 0], coords[3 * i + 1], coords[3 * i + 2], px, py, pz);

    out[4 * NPTS + 3 * i + 0] = px;
    out[4 * NPTS + 3 * i + 1] = py;
    out[4 * NPTS + 3 * i + 2] = pz;

    uint ix = (uint)min(GRID_R - 1, max(0, (int)((px + 1.0f) * 16.0f)));
    uint iy = (uint)min(GRID_R - 1, max(0, (int)((py + 1.0f) * 16.0f)));
    uint iz = (uint)min(GRID_R - 1, max(0, (int)((pz + 1.0f) * 16.0f)));
    uint cell = part1by2(ix) | (part1by2(iy) << 1) | (part1by2(iz) << 2);
    uint rank = atomicAdd(&g_cursor[cell], 1u);
    g_cellRank[i] = (cell << 17) | rank;
}

// ---- Pass C: single-block exclusive scan of 32768 counts (in place) ----
__global__ __launch_bounds__(1024)
void scan_kernel()
{
    __shared__ uint warpsum[32];
    const int t = threadIdx.x;
    const int lane = t & 31, wid = t >> 5;
    const int PER = NCELLS / 1024;   // 32

    uint v[PER];
    uint base_i = (uint)t * PER;
    uint local = 0;
#pragma unroll
    for (int j = 0; j < PER; j++) { v[j] = g_cursor[base_i + j]; local += v[j]; }

    uint x = local;
#pragma unroll
    for (int d = 1; d < 32; d <<= 1) {
        uint y = __shfl_up_sync(0xffffffffu, x, d);
        if (lane >= d) x += y;
    }
    if (lane == 31) warpsum[wid] = x;
    __syncthreads();
    if (wid == 0) {
        uint w = warpsum[lane];
#pragma unroll
        for (int d = 1; d < 32; d <<= 1) {
            uint y = __shfl_up_sync(0xffffffffu, w, d);
            if (lane >= d) w += y;
        }
        warpsum[lane] = w;
    }
    __syncthreads();
    uint base = (wid ? warpsum[wid - 1] : 0u) + (x - local);
#pragma unroll
    for (int j = 0; j < PER; j++) {
        g_cursor[base_i + j] = base;
        base += v[j];
    }
}

// ---- Pass D: ATOMIC-FREE scatter: pos = offset[cell] + rank; 8 pts/thread ----
__global__ __launch_bounds__(TPB)
void scatter_kernel(const float* __restrict__ coords)
{
    int g = blockIdx.x * TPB + threadIdx.x;
    int i0 = g * 8;
    float4 c4[6];
#pragma unroll
    for (int j = 0; j < 6; j++) c4[j] = ((const float4*)coords)[g * 6 + j];
    const float* cf = (const float*)c4;

    uint4 ra = ((const uint4*)g_cellRank)[g * 2 + 0];
    uint4 rb = ((const uint4*)g_cellRank)[g * 2 + 1];
    uint pk[8] = {ra.x, ra.y, ra.z, ra.w, rb.x, rb.y, rb.z, rb.w};

    uint pos[8];
#pragma unroll
    for (int j = 0; j < 8; j++)
        pos[j] = g_cursor[pk[j] >> 17] + (pk[j] & 0x1FFFFu);
#pragma unroll
    for (int j = 0; j < 8; j++) {
        float px, py, pz;
        warp_contract(cf[3 * j + 0], cf[3 * j + 1], cf[3 * j + 2], px, py, pz);
        g_sortedPts[pos[j]] = make_float4(px, py, pz, __int_as_float(i0 + j));
    }
}

// ---- Pass E: main blend; pair-packed distances + channel-packed updates ----
__global__ __launch_bounds__(TPB)
void main_kernel(float* __restrict__ out)
{
    __shared__ float4 cs0[NSTR];
    __shared__ float4 cs1[NSTR];
    __shared__ short  wlist[8][NSTR]; // per-warp surviving stroke indices
    __shared__ uint   wcnt[8];
    __shared__ float  red[8][6];

    const int tid = threadIdx.x;
    const int lane = tid & 31, wid = tid >> 5;
    // warp-contiguous layout: warp `wid` owns points [blk*1024 + wid*128, +128)
    const int base = blockIdx.x * PTS_PER_BLOCK + wid * 128 + lane;

    float px[PPT], py[PPT], pzv[PPT];
    int   orig[PPT];
    ull   hrg[PPT];
    ull   hbd[PPT];
    float w  [PPT];

    float mnx =  1e30f, mny =  1e30f, mnz =  1e30f;
    float mxx = -1e30f, mxy = -1e30f, mxz = -1e30f;

#pragma unroll
    for (int k = 0; k < PPT; k++) {
        float4 p = g_sortedPts[base + k * 32];
        px[k] = p.x; py[k] = p.y; pzv[k] = p.z;
        orig[k] = __float_as_int(p.w);
        hrg[k] = 0ULL; hbd[k] = 0ULL; w[k] = 1.0f;
        mnx = fminf(mnx, p.x); mxx = fmaxf(mxx, p.x);
        mny = fminf(mny, p.y); mxy = fmaxf(mxy, p.y);
        mnz = fminf(mnz, p.z); mxz = fmaxf(mxz, p.z);
    }

    // pair-packed positions: pair q holds points (2q, 2q+1)
    ull pXp[2], pYp[2], pZp[2];
#pragma unroll
    for (int q = 0; q < 2; q++) {
        pXp[q] = pk2(px[2*q], px[2*q+1]);
        pYp[q] = pk2(py[2*q], py[2*q+1]);
        pZp[q] = pk2(pzv[2*q], pzv[2*q+1]);
    }

    // warp bbox (128 contiguous sorted points -> tight)
#pragma unroll
    for (int d = 16; d; d >>= 1) {
        mnx = fminf(mnx, __shfl_xor_sync(0xffffffffu, mnx, d));
        mny = fminf(mny, __shfl_xor_sync(0xffffffffu, mny, d));
        mnz = fminf(mnz, __shfl_xor_sync(0xffffffffu, mnz, d));
        mxx = fmaxf(mxx, __shfl_xor_sync(0xffffffffu, mxx, d));
        mxy = fmaxf(mxy, __shfl_xor_sync(0xffffffffu, mxy, d));
        mxz = fmaxf(mxz, __shfl_xor_sync(0xffffffffu, mxz, d));
    }
    const float wmnx = mnx, wmny = mny, wmnz = mnz;
    const float wmxx = mxx, wmxy = mxy, wmxz = mxz;

    // block bbox for block-level compaction
    if (lane == 0) {
        red[wid][0] = mnx; red[wid][1] = mny; red[wid][2] = mnz;
        red[wid][3] = mxx; red[wid][4] = mxy; red[wid][5] = mxz;
    }
    __syncthreads();
#pragma unroll
    for (int ww = 0; ww < 8; ww++) {
        mnx = fminf(mnx, red[ww][0]); mny = fminf(mny, red[ww][1]); mnz = fminf(mnz, red[ww][2]);
        mxx = fmaxf(mxx, red[ww][3]); mxy = fmaxf(mxy, red[ww][4]); mxz = fmaxf(mxz, red[ww][5]);
    }
    __syncthreads();

    // ordered block compaction of strokes intersecting the BLOCK bbox
    int nlist = 0;
#pragma unroll 1
    for (int r = 0; r < 2; r++) {
        int s = r * TPB + tid;
        bool keep = false;
        float4 a0, a1;
        if (s < NSTR) {
            a0 = g_s0[s]; a1 = g_s1[s];
            float cx = -a0.x, cy = -a0.y, cz = -a1.z;
            float rr = a1.w * a1.w * 0.04f;   // (b/5)^2 = (r+0.1)^2
            float qx = fminf(fmaxf(cx, mnx), mxx);
            float qy = fminf(fmaxf(cy, mny), mxy);
            float qz = fminf(fmaxf(cz, mnz), mxz);
            float dx = cx - qx, dy = cy - qy, dz = cz - qz;
            float d2 = fmaf(dx, dx, fmaf(dy, dy, dz * dz));
            keep = d2 < rr;
        }
        uint m = __ballot_sync(0xffffffffu, keep);
        if (lane == 0) wcnt[wid] = (uint)__popc(m);
        __syncthreads();
        int off = nlist, tot = nlist;
#pragma unroll
        for (int ww = 0; ww < 8; ww++) {
            if (ww < wid) off += (int)wcnt[ww];
            tot += (int)wcnt[ww];
        }
        if (keep) {
            int pos = off + __popc(m & ((1u << lane) - 1u));
            cs0[pos] = a0;
            cs1[pos] = a1;
        }
        nlist = tot;
        __syncthreads();
    }

    // per-warp index compaction against the WARP bbox + full-cover truncation
    int wn = 0;
    int wstart = 0;
#pragma unroll 1
    for (int s0 = 0; s0 < nlist; s0 += 32) {
        int s = s0 + lane;
        bool keep = false, cover = false;
        if (s < nlist) {
            float4 a0 = cs0[s];
            float4 a1 = cs1[s];
            float cx = -a0.x, cy = -a0.y, cz = -a1.z;
            float rr = a1.w * a1.w * 0.04f;     // (r+0.1)^2
            float qx = fminf(fmaxf(cx, wmnx), wmxx);
            float qy = fminf(fmaxf(cy, wmny), wmxy);
            float qz = fminf(fmaxf(cz, wmnz), wmxz);
            float dx = cx - qx, dy = cy - qy, dz = cz - qz;
            float d2 = fmaf(dx, dx, fmaf(dy, dy, dz * dz));
            keep = d2 < rr;
            // farthest bbox corner inside radius (r-0.1)?  (b-1) = 5(r-0.1)
            float rm = a1.w - 1.0f;
            float fx = fmaxf(cx - wmnx, wmxx - cx);
            float fy = fmaxf(cy - wmny, wmxy - cy);
            float fz = fmaxf(cz - wmnz, wmxz - cz);
            float f2 = fmaf(fx, fx, fmaf(fy, fy, fz * fz));
            cover = (rm > 0.0f) && (25.0f * f2 < rm * rm);
        }
        uint m  = __ballot_sync(0xffffffffu, keep);
        uint cm = __ballot_sync(0xffffffffu, cover);
        if (keep)
            wlist[wid][wn + __popc(m & ((1u << lane) - 1u))] = (short)s;
        if (cm) {
            int lastLane = 31 - __clz(cm);
            wstart = wn + __popc(m & ((1u << lastLane) - 1u));
        }
        wn += __popc(m);
    }

    // sequential blend from the last full-cover stroke (order preserved)
#pragma unroll 1
    for (int j = wstart; j < wn; j++) {
        int s = wlist[wid][j];
        float4 s0 = cs0[s];
        float4 s1 = cs1[s];
        ull ncx2 = pk2(s0.x, s0.x);
        ull ncy2 = pk2(s0.y, s0.y);
        ull ncz2 = pk2(s1.z, s1.z);
        ull crg  = pk2(s0.z, s0.w);
        ull cbd  = pk2(s1.x, s1.y);
        float bb = s1.w;
#pragma unroll
        for (int q = 0; q < 2; q++) {
            // pair-packed distance for points (2q, 2q+1)
            ull dX = add2(pXp[q], ncx2);
            ull dY = add2(pYp[q], ncy2);
            ull dZ = add2(pZp[q], ncz2);
            ull d2p = fma2_(dZ, dZ, fma2_(dY, dY, mul2(dX, dX)));
            float d2a, d2b; upk2(d2p, d2a, d2b);
            float ta = fmasat_m5(sqap(d2a), bb);
            float tb = fmasat_m5(sqap(d2b), bb);
            // channel-packed updates (proven form)
            {
                int k = 2 * q;
                ull t2  = pk2(ta, ta);
                ull nt2 = t2 ^ 0x8000000080000000ULL;
                hrg[k] = fma2_(t2, crg, fma2_(nt2, hrg[k], hrg[k]));
                hbd[k] = fma2_(t2, cbd, fma2_(nt2, hbd[k], hbd[k]));
                w[k]   = fmaf(-ta, w[k], w[k]);
            }
            {
                int k = 2 * q + 1;
                ull t2  = pk2(tb, tb);
                ull nt2 = t2 ^ 0x8000000080000000ULL;
                hrg[k] = fma2_(t2, crg, fma2_(nt2, hrg[k], hrg[k]));
                hbd[k] = fma2_(t2, cbd, fma2_(nt2, hbd[k], hbd[k]));
                w[k]   = fmaf(-tb, w[k], w[k]);
            }
        }
    }

#pragma unroll
    for (int k = 0; k < PPT; k++) {
        int i = orig[k];
        float hr, hg, hb, hd;
        upk2(hrg[k], hr, hg);
        upk2(hbd[k], hb, hd);
        out[i] = hd;
        float inv = 1.0f / (1.0f + 1e-6f - w[k]);
        out[NPTS + 3 * i + 0] = __saturatef(hr * inv);
        out[NPTS + 3 * i + 1] = __saturatef(hg * inv);
        out[NPTS + 3 * i + 2] = __saturatef(hb * inv);
    }
}

extern "C" void kernel_launch(void* const* d_in, const int* in_sizes, int n_in,
                              void* d_out, int out_size)
{
    const float*  coords = (const float*)d_in[0];
    const float4* shape  = (const float4*)d_in[1];
    const float*  color  = (const float*)d_in[2];
    const float*  alpha  = (const float*)d_in[3];
    float* out = (float*)d_out;

    prep_kernel<<<(NCELLS + TPB - 1) / TPB, TPB>>>(shape, color, alpha);
    bin_kernel<<<NPTS / TPB, TPB>>>(coords, out);
    scan_kernel<<<1, 1024>>>();
    scatter_kernel<<<NPTS / (TPB * 8), TPB>>>(coords);
    main_kernel<<<NPTS / PTS_PER_BLOCK, TPB>>>(out);
}